// round 15
// baseline (speedup 1.0000x reference)
#include <cuda_runtime.h>
#include <cuda_pipeline.h>

#define DIM 1024
#define NROWS 32        // B*T = 2*16 distinct kv rows
#define TPF 1560        // tokens per frame

// Scratch (no cudaMalloc allowed): intermediate v and final per-frame y.
__device__ float g_v[NROWS * DIM];
__device__ float g_y[NROWS * DIM];

#define KCH 256                                   // K per X-pipeline chunk
#define NSTAGE 3
#define SW_FLOATS (8 * DIM)                       // full W tile: 8 cols x 1024 = 32KB
#define SX_STAGE_FLOATS (16 * KCH)                // X stage: 16 rows x 256 = 16KB
#define SMEM_BYTES ((SW_FLOATS + NSTAGE * SX_STAGE_FLOATS) * 4)   // 80KB

// ---- packed fp32x2 helpers (fp32-exact, halves FFMA issue count) ----
__device__ __forceinline__ unsigned long long pk(float lo, float hi) {
    unsigned long long r;
    asm("mov.b64 %0, {%1, %2};" : "=l"(r) : "f"(lo), "f"(hi));
    return r;
}
__device__ __forceinline__ void fma2(unsigned long long& a,
                                     unsigned long long x, unsigned long long w) {
    asm("fma.rn.f32x2 %0, %1, %2, %0;" : "+l"(a) : "l"(x), "l"(w));
}
__device__ __forceinline__ float2 unpk(unsigned long long a) {
    float lo, hi;
    asm("mov.b64 {%0, %1}, %2;" : "=f"(lo), "=f"(hi) : "l"(a));
    return make_float2(lo, hi);
}

// OUT[r, col] = sum_k IN[r, k] * W[col, k] + bias[col]
// IN: [32, 1024], W: [1024, 1024] row-major  (=> IN @ W^T + b)
//
// PDL-aware: the ENTIRE 32KB W tile is cp.async'd into smem in the pre-sync
// window (W does not depend on the predecessor), so for gemm2 the W DRAM
// fetch fully overlaps gemm1's execution. After GridDependencySynchronize,
// only the X tiles stream (3-stage ring; for gemm2 they're L2-hot v rows).
__global__ __launch_bounds__(256) void gemm32_kernel(
    const float* __restrict__ in,
    const float* __restrict__ W,
    const float* __restrict__ bias,
    float* __restrict__ out,
    int sync_dep)                     // 1: wait for predecessor before reading `in`
{
    extern __shared__ float s[];
    float* sW = s;                                    // [8][1024]
    float* sX = s + SW_FLOATS;                        // NSTAGE x [16][256]

    const int tid  = threadIdx.x;
    const int lane = tid & 31;
    const int warp = tid >> 5;
    const int rg   = warp & 3;
    const int cg   = warp >> 2;
    const int cb   = blockIdx.x & 127;       // col block (8 cols)
    const int rb   = blockIdx.x >> 7;        // row block (16 rows)
    const int row0 = rb * 16;
    const int col0 = cb * 8;

    // Release the dependent grid's launch immediately.
    cudaTriggerProgrammaticLaunchCompletion();

    // ---- PRE-SYNC: stage the full W tile (independent of predecessor) ----
    const float4* Wg  = reinterpret_cast<const float4*>(W + (size_t)col0 * DIM);
    float4*       sW4 = reinterpret_cast<float4*>(sW);
    #pragma unroll
    for (int f = tid; f < 8 * 256; f += 256)          // 2048 float4 = 32KB
        __pipeline_memcpy_async(&sW4[f], &Wg[f], 16);
    __pipeline_commit();                               // group A

    if (sync_dep) cudaGridDependencySynchronize();

    // ---- POST-SYNC: stream X through a 3-stage ring ----
    const float4* Xg = reinterpret_cast<const float4*>(in + (size_t)row0 * DIM);

    auto stage_x = [&](int ch, int st) {
        float4* sX4 = reinterpret_cast<float4*>(sX + st * SX_STAGE_FLOATS);
        const int k4 = ch * (KCH / 4);
        #pragma unroll
        for (int f = tid; f < 16 * 64; f += 256) {     // 1024 float4 = 16KB
            int r = f >> 6, j = f & 63;
            __pipeline_memcpy_async(&sX4[f], &Xg[(size_t)r * 256 + k4 + j], 16);
        }
        __pipeline_commit();
    };

    stage_x(0, 0);   // group B
    stage_x(1, 1);   // group C

    unsigned long long acc2[4][4];
    #pragma unroll
    for (int r = 0; r < 4; r++)
        #pragma unroll
        for (int c = 0; c < 4; c++) acc2[r][c] = 0ull;

    #pragma unroll
    for (int ch = 0; ch < 4; ch++) {
        const int st = ch % NSTAGE;
        // wait_prior(1) at ch=0 completes A (W) and B (X0); etc.
        __pipeline_wait_prior(ch < 3 ? 1 : 0);
        __syncthreads();
        if (ch < 2) stage_x(ch + 2, (ch + 2) % NSTAGE);

        const float* sXc = sX + st * SX_STAGE_FLOATS;     // [16][256]
        #pragma unroll
        for (int half = 0; half < 2; half++) {
            const int kl = half * 128 + lane * 4;          // k within chunk
            const int kg = ch * KCH + kl;                  // k within full row
            unsigned long long wlo[4], whi[4], xlo[4], xhi[4];
            #pragma unroll
            for (int c = 0; c < 4; c++) {
                float4 w = *reinterpret_cast<const float4*>(&sW[(cg * 4 + c) * DIM + kg]);
                wlo[c] = pk(w.x, w.y); whi[c] = pk(w.z, w.w);
            }
            #pragma unroll
            for (int r = 0; r < 4; r++) {
                float4 x = *reinterpret_cast<const float4*>(&sXc[(rg * 4 + r) * KCH + kl]);
                xlo[r] = pk(x.x, x.y); xhi[r] = pk(x.z, x.w);
            }
            #pragma unroll
            for (int r = 0; r < 4; r++)
                #pragma unroll
                for (int c = 0; c < 4; c++) {
                    fma2(acc2[r][c], xlo[r], wlo[c]);
                    fma2(acc2[r][c], xhi[r], whi[c]);
                }
        }
    }

    float acc[4][4];
    #pragma unroll
    for (int r = 0; r < 4; r++)
        #pragma unroll
        for (int c = 0; c < 4; c++) {
            float2 p = unpk(acc2[r][c]);
            acc[r][c] = p.x + p.y;
        }
    #pragma unroll
    for (int off = 16; off; off >>= 1)
        #pragma unroll
        for (int r = 0; r < 4; r++)
            #pragma unroll
            for (int c = 0; c < 4; c++)
                acc[r][c] += __shfl_xor_sync(0xffffffffu, acc[r][c], off);

    float res = 0.0f;
    #pragma unroll
    for (int r = 0; r < 4; r++)
        #pragma unroll
        for (int c = 0; c < 4; c++)
            if (lane == r * 4 + c) res = acc[r][c];

    if (lane < 16) {
        const int r = lane >> 2, c = lane & 3;
        const int grow = row0 + rg * 4 + r;
        const int gcol = col0 + cg * 4 + c;
        out[grow * DIM + gcol] = res + bias[gcol];
    }
}

// Broadcast y[frame, :] to all 1560 rows of the frame (streaming stores; at
// the chip store cap). PDL-launched: wave setup overlaps gemm2's execution.
__global__ __launch_bounds__(256) void bcast_kernel(
    const float4* __restrict__ y4,
    float4* __restrict__ out4)
{
    cudaGridDependencySynchronize();

    const int f   = blockIdx.y;                  // frame 0..31
    const int tid = threadIdx.x;
    const float4 val = y4[f * 256 + tid];

    const int per_frame = TPF * 256;             // 399,360 float4 per frame
    const long base = (long)f * per_frame;
    const int stride = gridDim.x * 256;

    for (int i = blockIdx.x * 256 + tid; i < per_frame; i += stride) {
        __stcs(&out4[base + i], val);
    }
}

extern "C" void kernel_launch(void* const* d_in, const int* in_sizes, int n_in,
                              void* d_out, int out_size)
{
    // metadata order: x, c, Wq, bq, Wk, bk, Wv, bv, Wo, bo
    // softmax over a length-1 kv axis is identically 1 -> x/Wq/bq/Wk/bk unused.
    const float* c  = (const float*)d_in[1];
    const float* Wv = (const float*)d_in[6];
    const float* bv = (const float*)d_in[7];
    const float* Wo = (const float*)d_in[8];
    const float* bo = (const float*)d_in[9];
    float* out = (float*)d_out;

    void* vptr = nullptr;
    void* yptr = nullptr;
    cudaGetSymbolAddress(&vptr, g_v);
    cudaGetSymbolAddress(&yptr, g_y);
    float* v = (float*)vptr;
    float* y = (float*)yptr;

    cudaFuncSetAttribute(gemm32_kernel,
                         cudaFuncAttributeMaxDynamicSharedMemorySize, SMEM_BYTES);

    // gemm1: plain launch (no predecessor inside the replay).
    gemm32_kernel<<<256, 256, SMEM_BYTES>>>(c, Wv, bv, v, 0);

    // gemm2 + bcast: PDL so each launches during its predecessor's execution.
    cudaLaunchAttribute attr;
    attr.id = cudaLaunchAttributeProgrammaticStreamSerialization;
    attr.val.programmaticStreamSerializationAllowed = 1;

    {
        cudaLaunchConfig_t cfg = {};
        cfg.gridDim = dim3(256); cfg.blockDim = dim3(256);
        cfg.dynamicSmemBytes = SMEM_BYTES; cfg.stream = 0;
        cfg.attrs = &attr; cfg.numAttrs = 1;
        const float* in2 = v; int sd = 1;
        cudaError_t e = cudaLaunchKernelEx(&cfg, gemm32_kernel,
                                           in2, Wo, bo, y, sd);
        if (e != cudaSuccess) {   // fallback: plain launch (still correct)
            gemm32_kernel<<<256, 256, SMEM_BYTES>>>(v, Wo, bo, y, 1);
        }
    }
    {
        cudaLaunchConfig_t cfg = {};
        cfg.gridDim = dim3(130, 32); cfg.blockDim = dim3(256);
        cfg.dynamicSmemBytes = 0; cfg.stream = 0;
        cfg.attrs = &attr; cfg.numAttrs = 1;
        const float4* y4 = (const float4*)y; float4* o4 = (float4*)out;
        cudaError_t e = cudaLaunchKernelEx(&cfg, bcast_kernel, y4, o4);
        if (e != cudaSuccess) {
            bcast_kernel<<<dim3(130, 32), 256>>>((const float4*)y, (float4*)out);
        }
    }

    (void)in_sizes; (void)n_in; (void)out_size;
}

// round 16
// speedup vs baseline: 1.4517x; 1.4517x over previous
#include <cuda_runtime.h>
#include <cuda_pipeline.h>

#define DIM 1024
#define NROWS 32        // B*T = 2*16 distinct kv rows
#define TPF 1560        // tokens per frame

// Scratch (no cudaMalloc allowed): intermediate v and final per-frame y.
__device__ float g_v[NROWS * DIM];
__device__ float g_y[NROWS * DIM];

#define KCH 256                               // K per pipeline chunk
#define NSTAGE 3
#define STAGE_FLOATS ((8 + 16) * KCH)         // 24KB per stage
#define SMEM_BYTES (NSTAGE * STAGE_FLOATS * 4)  // 72KB ring

// ---- packed fp32x2 helpers (fp32-exact, halves FFMA issue count) ----
__device__ __forceinline__ unsigned long long pk(float lo, float hi) {
    unsigned long long r;
    asm("mov.b64 %0, {%1, %2};" : "=l"(r) : "f"(lo), "f"(hi));
    return r;
}
__device__ __forceinline__ void fma2(unsigned long long& a,
                                     unsigned long long x, unsigned long long w) {
    asm("fma.rn.f32x2 %0, %1, %2, %0;" : "+l"(a) : "l"(x), "l"(w));
}
__device__ __forceinline__ float2 unpk(unsigned long long a) {
    float lo, hi;
    asm("mov.b64 {%0, %1}, %2;" : "=f"(lo), "=f"(hi) : "l"(a));
    return make_float2(lo, hi);
}

// OUT[r, col] = sum_k IN[r, k] * W[col, k] + bias[col]   (proven R9/R14 body:
// interleaved W+X 24KB stages, 3-stage cp.async ring, f32x2 inner product).
// trig_late=0: release dependent grid at entry (used by gemm1 -> gemm2;
//              gemm2's CTAs only take slots as gemm1's retire, no contention).
// trig_late=1: release dependent grid AFTER the mainloop (used by gemm2 ->
//              bcast; avoids the 4160-CTA bcast wave setup competing with
//              gemm2's compute, while still hiding it in gemm2's tail).
__global__ __launch_bounds__(256) void gemm32_kernel(
    const float* __restrict__ in,
    const float* __restrict__ W,
    const float* __restrict__ bias,
    float* __restrict__ out,
    const float* __restrict__ pf,     // weight tile to L2-prefetch (or null)
    int sync_dep,                     // 1: wait for predecessor before reading `in`
    int trig_late)                    // see above
{
    extern __shared__ float s[];

    const int tid  = threadIdx.x;
    const int lane = tid & 31;
    const int warp = tid >> 5;
    const int rg   = warp & 3;
    const int cg   = warp >> 2;
    const int cb   = blockIdx.x & 127;       // col block (8 cols)
    const int rb   = blockIdx.x >> 7;        // row block (16 rows)
    const int row0 = rb * 16;
    const int col0 = cb * 8;

    if (!trig_late) cudaTriggerProgrammaticLaunchCompletion();

    // Pre-sync work: L2-prefetch a weight tile (no dependency on predecessor).
    if (pf) {
        const char* base = reinterpret_cast<const char*>(pf) + (size_t)col0 * DIM * 4;
        asm volatile("prefetch.global.L2 [%0];" :: "l"(base + tid * 128));
    }

    if (sync_dep) cudaGridDependencySynchronize();

    const float4* Wg = reinterpret_cast<const float4*>(W + (size_t)col0 * DIM);
    const float4* Xg = reinterpret_cast<const float4*>(in + (size_t)row0 * DIM);

    auto stage_chunk = [&](int ch, int st) {
        float4* sW4 = reinterpret_cast<float4*>(s + st * STAGE_FLOATS);
        float4* sX4 = sW4 + 8 * (KCH / 4);
        const int k4 = ch * (KCH / 4);
        #pragma unroll
        for (int f = tid; f < 8 * 64; f += 256) {
            int c = f >> 6, j = f & 63;
            __pipeline_memcpy_async(&sW4[f], &Wg[(size_t)c * 256 + k4 + j], 16);
        }
        #pragma unroll
        for (int f = tid; f < 16 * 64; f += 256) {
            int r = f >> 6, j = f & 63;
            __pipeline_memcpy_async(&sX4[f], &Xg[(size_t)r * 256 + k4 + j], 16);
        }
        __pipeline_commit();
    };

    stage_chunk(0, 0);
    stage_chunk(1, 1);

    unsigned long long acc2[4][4];
    #pragma unroll
    for (int r = 0; r < 4; r++)
        #pragma unroll
        for (int c = 0; c < 4; c++) acc2[r][c] = 0ull;

    #pragma unroll
    for (int ch = 0; ch < 4; ch++) {
        const int st = ch % NSTAGE;
        __pipeline_wait_prior(ch < 3 ? 1 : 0);
        __syncthreads();
        if (ch < 2) stage_chunk(ch + 2, (ch + 2) % NSTAGE);

        const float* sW = s + st * STAGE_FLOATS;          // [8][256]
        const float* sX = sW + 8 * KCH;                   // [16][256]
        #pragma unroll
        for (int half = 0; half < 2; half++) {
            const int k = half * 128 + lane * 4;
            unsigned long long wlo[4], whi[4], xlo[4], xhi[4];
            #pragma unroll
            for (int c = 0; c < 4; c++) {
                float4 w = *reinterpret_cast<const float4*>(&sW[(cg * 4 + c) * KCH + k]);
                wlo[c] = pk(w.x, w.y); whi[c] = pk(w.z, w.w);
            }
            #pragma unroll
            for (int r = 0; r < 4; r++) {
                float4 x = *reinterpret_cast<const float4*>(&sX[(rg * 4 + r) * KCH + k]);
                xlo[r] = pk(x.x, x.y); xhi[r] = pk(x.z, x.w);
            }
            #pragma unroll
            for (int r = 0; r < 4; r++)
                #pragma unroll
                for (int c = 0; c < 4; c++) {
                    fma2(acc2[r][c], xlo[r], wlo[c]);
                    fma2(acc2[r][c], xhi[r], whi[c]);
                }
        }
    }

    // Mainloop done: release the dependent grid now (epilogue remains).
    if (trig_late) cudaTriggerProgrammaticLaunchCompletion();

    float acc[4][4];
    #pragma unroll
    for (int r = 0; r < 4; r++)
        #pragma unroll
        for (int c = 0; c < 4; c++) {
            float2 p = unpk(acc2[r][c]);
            acc[r][c] = p.x + p.y;
        }
    #pragma unroll
    for (int off = 16; off; off >>= 1)
        #pragma unroll
        for (int r = 0; r < 4; r++)
            #pragma unroll
            for (int c = 0; c < 4; c++)
                acc[r][c] += __shfl_xor_sync(0xffffffffu, acc[r][c], off);

    float res = 0.0f;
    #pragma unroll
    for (int r = 0; r < 4; r++)
        #pragma unroll
        for (int c = 0; c < 4; c++)
            if (lane == r * 4 + c) res = acc[r][c];

    if (lane < 16) {
        const int r = lane >> 2, c = lane & 3;
        const int grow = row0 + rg * 4 + r;
        const int gcol = col0 + cg * 4 + c;
        out[grow * DIM + gcol] = res + bias[gcol];
    }
}

// Broadcast y[frame, :] to all 1560 rows of the frame (streaming stores; at
// the chip store cap). PDL-launched: wave setup overlaps gemm2's tail.
__global__ __launch_bounds__(256) void bcast_kernel(
    const float4* __restrict__ y4,
    float4* __restrict__ out4)
{
    cudaGridDependencySynchronize();

    const int f   = blockIdx.y;                  // frame 0..31
    const int tid = threadIdx.x;
    const float4 val = y4[f * 256 + tid];

    const int per_frame = TPF * 256;             // 399,360 float4 per frame
    const long base = (long)f * per_frame;
    const int stride = gridDim.x * 256;

    for (int i = blockIdx.x * 256 + tid; i < per_frame; i += stride) {
        __stcs(&out4[base + i], val);
    }
}

extern "C" void kernel_launch(void* const* d_in, const int* in_sizes, int n_in,
                              void* d_out, int out_size)
{
    // metadata order: x, c, Wq, bq, Wk, bk, Wv, bv, Wo, bo
    // softmax over a length-1 kv axis is identically 1 -> x/Wq/bq/Wk/bk unused.
    const float* c  = (const float*)d_in[1];
    const float* Wv = (const float*)d_in[6];
    const float* bv = (const float*)d_in[7];
    const float* Wo = (const float*)d_in[8];
    const float* bo = (const float*)d_in[9];
    float* out = (float*)d_out;

    void* vptr = nullptr;
    void* yptr = nullptr;
    cudaGetSymbolAddress(&vptr, g_v);
    cudaGetSymbolAddress(&yptr, g_y);
    float* v = (float*)vptr;
    float* y = (float*)yptr;

    cudaFuncSetAttribute(gemm32_kernel,
                         cudaFuncAttributeMaxDynamicSharedMemorySize, SMEM_BYTES);

    // gemm1: plain launch; releases gemm2 at entry (entry trigger is safe
    // here -- gemm2's CTAs only get SM slots as gemm1's retire).
    gemm32_kernel<<<256, 256, SMEM_BYTES>>>(c, Wv, bv, v, Wo, 0, 0);

    // gemm2 + bcast: PDL so each launches during its predecessor's execution.
    cudaLaunchAttribute attr;
    attr.id = cudaLaunchAttributeProgrammaticStreamSerialization;
    attr.val.programmaticStreamSerializationAllowed = 1;

    {
        cudaLaunchConfig_t cfg = {};
        cfg.gridDim = dim3(256); cfg.blockDim = dim3(256);
        cfg.dynamicSmemBytes = SMEM_BYTES; cfg.stream = 0;
        cfg.attrs = &attr; cfg.numAttrs = 1;
        const float* in2 = v; const float* pf2 = Wo; int sd = 1, tl = 1;
        cudaError_t e = cudaLaunchKernelEx(&cfg, gemm32_kernel,
                                           in2, Wo, bo, y, pf2, sd, tl);
        if (e != cudaSuccess) {   // fallback: plain launch (still correct)
            gemm32_kernel<<<256, 256, SMEM_BYTES>>>(v, Wo, bo, y, Wo, 1, 1);
        }
    }
    {
        cudaLaunchConfig_t cfg = {};
        cfg.gridDim = dim3(130, 32); cfg.blockDim = dim3(256);
        cfg.dynamicSmemBytes = 0; cfg.stream = 0;
        cfg.attrs = &attr; cfg.numAttrs = 1;
        const float4* y4 = (const float4*)y; float4* o4 = (float4*)out;
        cudaError_t e = cudaLaunchKernelEx(&cfg, bcast_kernel, y4, o4);
        if (e != cudaSuccess) {
            bcast_kernel<<<dim3(130, 32), 256>>>((const float4*)y, (float4*)out);
        }
    }

    (void)in_sizes; (void)n_in; (void)out_size;
}